// round 9
// baseline (speedup 1.0000x reference)
#include <cuda_runtime.h>
#include <cuda_bf16.h>
#include <cstdint>

static constexpr int Bb = 256;
static constexpr int Aa = 32;
static constexpr int Dd = 2048;

// ---------------- device scratch (allocation-free rule) ----------------
__device__ __nv_bfloat16 g_Ahi[Bb * Dd];
__device__ __nv_bfloat16 g_Alo[Bb * Dd];
__device__ __nv_bfloat16 g_Whi[Dd * Dd];    // [k][n] native layout, hi part
__device__ __nv_bfloat16 g_Wlo[Dd * Dd];    // [k][n] native layout, lo part
__device__ float g_part[3][Bb * Dd];        // per-term fp32 partials

// ---------------- PTX helpers (baseline sm_80+ features only) ----------
__device__ __forceinline__ uint32_t smem_u32(const void* p) {
    uint32_t a;
    asm("{ .reg .u64 t; cvta.to.shared.u64 t, %1; cvt.u32.u64 %0, t; }"
        : "=r"(a) : "l"(p));
    return a;
}
__device__ __forceinline__ void cp_async16(uint32_t dst, const void* src) {
    asm volatile("cp.async.cg.shared.global [%0], [%1], 16;"
                 :: "r"(dst), "l"(src) : "memory");
}
__device__ __forceinline__ void cp_commit() {
    asm volatile("cp.async.commit_group;" ::: "memory");
}
__device__ __forceinline__ void ldsm4(uint32_t& r0, uint32_t& r1, uint32_t& r2,
                                      uint32_t& r3, uint32_t addr) {
    asm volatile("ldmatrix.sync.aligned.m8n8.x4.shared.b16 {%0,%1,%2,%3}, [%4];"
                 : "=r"(r0), "=r"(r1), "=r"(r2), "=r"(r3) : "r"(addr));
}
__device__ __forceinline__ void ldsm4t(uint32_t& r0, uint32_t& r1, uint32_t& r2,
                                       uint32_t& r3, uint32_t addr) {
    asm volatile("ldmatrix.sync.aligned.m8n8.x4.trans.shared.b16 {%0,%1,%2,%3}, [%4];"
                 : "=r"(r0), "=r"(r1), "=r"(r2), "=r"(r3) : "r"(addr));
}
__device__ __forceinline__ void mma16816(float* d, const uint32_t* a,
                                         uint32_t b0, uint32_t b1) {
    asm volatile(
        "mma.sync.aligned.m16n8k16.row.col.f32.bf16.bf16.f32 "
        "{%0,%1,%2,%3}, {%4,%5,%6,%7}, {%8,%9}, {%0,%1,%2,%3};"
        : "+f"(d[0]), "+f"(d[1]), "+f"(d[2]), "+f"(d[3])
        : "r"(a[0]), "r"(a[1]), "r"(a[2]), "r"(a[3]), "r"(b0), "r"(b1));
}
__device__ __forceinline__ float4 ldcs4(const float4* p) {
    float4 v;
    asm volatile("ld.global.cs.v4.f32 {%0,%1,%2,%3}, [%4];"
                 : "=f"(v.x), "=f"(v.y), "=f"(v.z), "=f"(v.w) : "l"(p));
    return v;
}

// ---------------------------------------------------------------------------
// prep: blocks [0,512): masked agg -> A_hi/A_lo (2 blocks per sample);
//       blocks [512,1536): streaming W fp32 -> bf16 hi/lo (4 float4/thread).
// Single-use global reads use .cs so they don't evict the W bf16 planes.
// ---------------------------------------------------------------------------
static constexpr int AGG_BLKS = 512;         // 2 per sample
static constexpr int CVT_BLKS = 1024;        // (Dd*Dd/4) / (256*4)

__global__ __launch_bounds__(256) void prep_kernel(
    const float* __restrict__ feat,
    const void* __restrict__ label_raw,
    const float* __restrict__ W)
{
    int bid = blockIdx.x;

    if (bid < AGG_BLKS) {
        __shared__ int s_idx[32];
        __shared__ int s_n;
        int b = bid >> 1;
        int half = bid & 1;

        if (threadIdx.x < 32) {
            // int64 labels (values 0/1) have all odd 32-bit words zero
            const int* l32 = (const int*)label_raw;
            int nz = 0;
            for (int i = threadIdx.x; i < 64; i += 32)
                if (l32[2 * i + 1] != 0) nz = 1;
            unsigned any = __ballot_sync(0xffffffffu, nz);
            int is_i64 = (any == 0u);

            int pred;
            if (is_i64) {
                const long long* l = (const long long*)label_raw;
                pred = (l[(size_t)b * Aa + threadIdx.x] > 0);
            } else {
                const int* l = (const int*)label_raw;
                pred = (l[(size_t)b * Aa + threadIdx.x] > 0);
            }
            unsigned m = __ballot_sync(0xffffffffu, pred);
            if (pred) s_idx[__popc(m & ((1u << threadIdx.x) - 1u))] = threadIdx.x;
            if (threadIdx.x == 0) s_n = __popc(m);
        }
        __syncthreads();
        int nact = s_n;

        const float4* f4 = reinterpret_cast<const float4*>(feat) + (size_t)b * Aa * (Dd / 4);
        __nv_bfloat162* hi2 = reinterpret_cast<__nv_bfloat162*>(g_Ahi + (size_t)b * Dd);
        __nv_bfloat162* lo2 = reinterpret_cast<__nv_bfloat162*>(g_Alo + (size_t)b * Dd);

        int i = half * 256 + threadIdx.x;     // float4 index within row (0..511)
        float4 s = make_float4(0.f, 0.f, 0.f, 0.f);
#pragma unroll 4
        for (int j = 0; j < nact; j++) {
            float4 v = ldcs4(&f4[(size_t)s_idx[j] * (Dd / 4) + i]);
            s.x += v.x; s.y += v.y; s.z += v.z; s.w += v.w;
        }
        float vals[4] = {s.x, s.y, s.z, s.w};
        __nv_bfloat16 h[4], l[4];
#pragma unroll
        for (int j = 0; j < 4; j++) {
            h[j] = __float2bfloat16(vals[j]);
            l[j] = __float2bfloat16(vals[j] - __bfloat162float(h[j]));
        }
        hi2[i * 2 + 0] = __nv_bfloat162(h[0], h[1]);
        hi2[i * 2 + 1] = __nv_bfloat162(h[2], h[3]);
        lo2[i * 2 + 0] = __nv_bfloat162(l[0], l[1]);
        lo2[i * 2 + 1] = __nv_bfloat162(l[2], l[3]);
    } else {
        // pure streaming convert: 4 float4 per thread
        const float4* W4 = (const float4*)W;
        __nv_bfloat162* hi2 = (__nv_bfloat162*)g_Whi;
        __nv_bfloat162* lo2 = (__nv_bfloat162*)g_Wlo;
        int base = (bid - AGG_BLKS) * 1024 + threadIdx.x;
#pragma unroll
        for (int u = 0; u < 4; u++) {
            int i = base + u * 256;
            float4 w = ldcs4(&W4[i]);
            float vals[4] = {w.x, w.y, w.z, w.w};
            __nv_bfloat16 h[4], l[4];
#pragma unroll
            for (int j = 0; j < 4; j++) {
                h[j] = __float2bfloat16(vals[j]);
                l[j] = __float2bfloat16(vals[j] - __bfloat162float(h[j]));
            }
            hi2[i * 2 + 0] = __nv_bfloat162(h[0], h[1]);
            hi2[i * 2 + 1] = __nv_bfloat162(h[2], h[3]);
            lo2[i * 2 + 0] = __nv_bfloat162(l[0], l[1]);
            lo2[i * 2 + 1] = __nv_bfloat162(l[2], l[3]);
        }
    }
}

// ---------------------------------------------------------------------------
// bf16 GEMM via mma.sync, ONE split-term per CTA.z -> fp32 partials.
// CTA tile 128(m) x 64(n), 8 warps = 4(m) x 2(n), NO k-split (each warp does
// both k16 steps of a k32 chunk). 64 chunks, 4-stage cp.async pipeline with
// exactly one commit-group per iteration (empty commit in tail).
// A SMEM: [m128][k32] 64B rows. B SMEM: [k32][n64] 128B rows (ldmatrix.trans).
// Grid 32 x 2 x 3 = 192 CTAs, 48KB smem -> 2 CTA/SM.
// ---------------------------------------------------------------------------
static constexpr int STAGE_BYTES = 12288;    // A 8KB + B 4KB
static constexpr int NSTAGE = 4;
static constexpr int NCHUNK = 64;            // 2048 / 32

__global__ __launch_bounds__(256) void gemm_kernel() {
    __shared__ __align__(128) char smbuf[NSTAGE * STAGE_BYTES];   // 48 KB
    const uint32_t sbase = smem_u32(smbuf);

    const int tid = threadIdx.x;
    const int lane = tid & 31;
    const int wid = tid >> 5;
    const int wm = wid >> 1;          // warp m (0..3)
    const int wn = wid & 1;           // warp n (0..1)

    const int m0 = blockIdx.y * 128;
    const int n0 = blockIdx.x * 64;
    const int term = blockIdx.z;      // 0: Ahi*Whi, 1: Ahi*Wlo, 2: Alo*Whi

    const __nv_bfloat16* Ap = (term == 2) ? g_Alo : g_Ahi;
    const __nv_bfloat16* Bp = (term == 1) ? g_Wlo : g_Whi;
    const __nv_bfloat16* Ag = Ap + (size_t)m0 * Dd;           // [m][k]
    const __nv_bfloat16* Bg = Bp + n0;                        // [k][n] col slice

    const int g = lane >> 3;
    const int lr = lane & 7;

    // ldmatrix A offsets: rows 64B, swizzle c^((row>>1)&3). [mt][ks]
    uint32_t offA[2][2];
#pragma unroll
    for (int mt = 0; mt < 2; mt++) {
        int row = wm * 32 + mt * 16 + (g & 1) * 8 + lr;
#pragma unroll
        for (int ks = 0; ks < 2; ks++) {
            int c = 2 * ks + (g >> 1);
            offA[mt][ks] = row * 64 + ((c ^ ((row >> 1) & 3)) << 4);
        }
    }
    // ldmatrix B offsets (trans): [k32][n64] 128B rows, swizzle c^(krow&7). [ks][p]
    uint32_t offB[2][2];
#pragma unroll
    for (int ks = 0; ks < 2; ks++) {
        int krow = ks * 16 + (g & 1) * 8 + lr;
#pragma unroll
        for (int p = 0; p < 2; p++) {
            int c = wn * 4 + 2 * p + (g >> 1);
            offB[ks][p] = krow * 128 + ((c ^ (krow & 7)) << 4);
        }
    }

    // cp.async assignments: A 8KB = 512x16B -> 2/thread; B 4KB = 256x16B -> 1/thread
    const int arow = tid >> 2, ac = tid & 3;
    const uint32_t aoff = arow * 64 + ((ac ^ ((arow >> 1) & 3)) << 4);
    const int brow = tid >> 3, bc = tid & 7;
    const uint32_t boff = brow * 128 + ((bc ^ (brow & 7)) << 4);

    auto issue_load = [&](int chunk) {
        int kt = chunk * 32;
        uint32_t st = sbase + (chunk & (NSTAGE - 1)) * STAGE_BYTES;
        cp_async16(st + aoff, Ag + (size_t)arow * Dd + kt + ac * 8);
        cp_async16(st + aoff + 4096, Ag + (size_t)(arow + 64) * Dd + kt + ac * 8);
        cp_async16(st + 8192 + boff, Bg + (size_t)(kt + brow) * Dd + bc * 8);
        cp_commit();
    };

    float acc[2][4][4];
#pragma unroll
    for (int mt = 0; mt < 2; mt++)
#pragma unroll
        for (int nf = 0; nf < 4; nf++)
#pragma unroll
            for (int k = 0; k < 4; k++) acc[mt][nf][k] = 0.f;

    issue_load(0); issue_load(1); issue_load(2);

    for (int i = 0; i < NCHUNK; i++) {
        // chunk i's group was committed 3 iterations ago; with exactly one
        // commit per iteration, wait_group 2 guarantees stage i has landed.
        asm volatile("cp.async.wait_group 2;" ::: "memory");
        __syncthreads();
        if (i + 3 < NCHUNK) issue_load(i + 3);
        else cp_commit();                      // empty group keeps accounting exact

        uint32_t sA = sbase + (i & (NSTAGE - 1)) * STAGE_BYTES;
        uint32_t sB = sA + 8192;

#pragma unroll
        for (int ks = 0; ks < 2; ks++) {
            uint32_t a[2][4], b[2][4];
            ldsm4(a[0][0], a[0][1], a[0][2], a[0][3], sA + offA[0][ks]);
            ldsm4(a[1][0], a[1][1], a[1][2], a[1][3], sA + offA[1][ks]);
            ldsm4t(b[0][0], b[0][1], b[0][2], b[0][3], sB + offB[ks][0]);
            ldsm4t(b[1][0], b[1][1], b[1][2], b[1][3], sB + offB[ks][1]);

#pragma unroll
            for (int mt = 0; mt < 2; mt++) {
                mma16816(acc[mt][0], a[mt], b[0][0], b[0][1]);
                mma16816(acc[mt][1], a[mt], b[0][2], b[0][3]);
                mma16816(acc[mt][2], a[mt], b[1][0], b[1][1]);
                mma16816(acc[mt][3], a[mt], b[1][2], b[1][3]);
            }
        }
    }
    asm volatile("cp.async.wait_group 0;" ::: "memory");

    // direct epilogue (no k-split): each warp owns rows [wm*32, wm*32+32)
    float* gp = g_part[term];
#pragma unroll
    for (int mt = 0; mt < 2; mt++)
#pragma unroll
        for (int nf = 0; nf < 4; nf++) {
            int grow = m0 + wm * 32 + mt * 16 + (lane >> 2);
            int gcol = n0 + wn * 32 + nf * 8 + (lane & 3) * 2;
            *(float2*)&gp[(size_t)grow * Dd + gcol] =
                make_float2(acc[mt][nf][0], acc[mt][nf][1]);
            *(float2*)&gp[(size_t)(grow + 8) * Dd + gcol] =
                make_float2(acc[mt][nf][2], acc[mt][nf][3]);
        }
}

// ---------------------------------------------------------------------------
// finish: out = tanh(p0 + p1 + p2 + bias)
// ---------------------------------------------------------------------------
__global__ __launch_bounds__(256) void finish_kernel(
    const float* __restrict__ bias, float* __restrict__ out)
{
    int idx = blockIdx.x * 256 + threadIdx.x;        // float4 index
    const float4* p0 = (const float4*)g_part[0];
    const float4* p1 = (const float4*)g_part[1];
    const float4* p2 = (const float4*)g_part[2];
    int n4 = idx & (Dd / 4 - 1);
    float4 a = p0[idx], b = p1[idx], c = p2[idx];
    float4 bv = ((const float4*)bias)[n4];
    float4 r;
    r.x = tanhf(a.x + b.x + c.x + bv.x);
    r.y = tanhf(a.y + b.y + c.y + bv.y);
    r.z = tanhf(a.z + b.z + c.z + bv.z);
    r.w = tanhf(a.w + b.w + c.w + bv.w);
    ((float4*)out)[idx] = r;
}

// ---------------------------------------------------------------------------
// launch: inputs x, attribute_feat, attribute_label, W, b  (x unused: adj[A][A]=0)
// ---------------------------------------------------------------------------
extern "C" void kernel_launch(void* const* d_in, const int* in_sizes, int n_in,
                              void* d_out, int out_size) {
    (void)in_sizes; (void)n_in; (void)out_size;
    const float* feat  = (const float*)d_in[1];
    const void*  label = d_in[2];
    const float* W     = (const float*)d_in[3];
    const float* bias  = (const float*)d_in[4];
    float* out = (float*)d_out;

    prep_kernel<<<AGG_BLKS + CVT_BLKS, 256>>>(feat, label, W);
    gemm_kernel<<<dim3(Dd / 64, Bb / 128, 3), 256>>>();
    finish_kernel<<<(Bb * Dd / 4) / 256, 256>>>(bias, out);
}

// round 10
// speedup vs baseline: 1.1519x; 1.1519x over previous
#include <cuda_runtime.h>
#include <cuda_bf16.h>
#include <cstdint>

static constexpr int Bb = 256;
static constexpr int Aa = 32;
static constexpr int Dd = 2048;

// ---------------- device scratch (allocation-free rule) ----------------
__device__ __nv_bfloat16 g_Ahi[Bb * Dd];
__device__ __nv_bfloat16 g_Alo[Bb * Dd];
__device__ __nv_bfloat16 g_Whi[Dd * Dd];    // [k][n] native layout, hi part
__device__ __nv_bfloat16 g_Wlo[Dd * Dd];    // [k][n] native layout, lo part
__device__ float g_part[12][Bb * Dd];       // per-(term,ksplit) fp32 partials

// ---------------- PTX helpers (baseline sm_80+ features only) ----------
__device__ __forceinline__ uint32_t smem_u32(const void* p) {
    uint32_t a;
    asm("{ .reg .u64 t; cvta.to.shared.u64 t, %1; cvt.u32.u64 %0, t; }"
        : "=r"(a) : "l"(p));
    return a;
}
__device__ __forceinline__ void cp_async16(uint32_t dst, const void* src) {
    asm volatile("cp.async.cg.shared.global [%0], [%1], 16;"
                 :: "r"(dst), "l"(src) : "memory");
}
__device__ __forceinline__ void cp_commit() {
    asm volatile("cp.async.commit_group;" ::: "memory");
}
__device__ __forceinline__ void ldsm4(uint32_t& r0, uint32_t& r1, uint32_t& r2,
                                      uint32_t& r3, uint32_t addr) {
    asm volatile("ldmatrix.sync.aligned.m8n8.x4.shared.b16 {%0,%1,%2,%3}, [%4];"
                 : "=r"(r0), "=r"(r1), "=r"(r2), "=r"(r3) : "r"(addr));
}
__device__ __forceinline__ void ldsm4t(uint32_t& r0, uint32_t& r1, uint32_t& r2,
                                       uint32_t& r3, uint32_t addr) {
    asm volatile("ldmatrix.sync.aligned.m8n8.x4.trans.shared.b16 {%0,%1,%2,%3}, [%4];"
                 : "=r"(r0), "=r"(r1), "=r"(r2), "=r"(r3) : "r"(addr));
}
__device__ __forceinline__ void mma16816(float* d, const uint32_t* a,
                                         uint32_t b0, uint32_t b1) {
    asm volatile(
        "mma.sync.aligned.m16n8k16.row.col.f32.bf16.bf16.f32 "
        "{%0,%1,%2,%3}, {%4,%5,%6,%7}, {%8,%9}, {%0,%1,%2,%3};"
        : "+f"(d[0]), "+f"(d[1]), "+f"(d[2]), "+f"(d[3])
        : "r"(a[0]), "r"(a[1]), "r"(a[2]), "r"(a[3]), "r"(b0), "r"(b1));
}
__device__ __forceinline__ float4 ldcs4(const float4* p) {
    float4 v;
    asm volatile("ld.global.cs.v4.f32 {%0,%1,%2,%3}, [%4];"
                 : "=f"(v.x), "=f"(v.y), "=f"(v.z), "=f"(v.w) : "l"(p));
    return v;
}

// ---------------------------------------------------------------------------
// prep: blocks [0,512): masked agg -> A_hi/A_lo (2 blocks per sample);
//       blocks [512,1536): streaming W fp32 -> bf16 hi/lo (4 float4/thread).
// ---------------------------------------------------------------------------
static constexpr int AGG_BLKS = 512;
static constexpr int CVT_BLKS = 1024;

__global__ __launch_bounds__(256) void prep_kernel(
    const float* __restrict__ feat,
    const void* __restrict__ label_raw,
    const float* __restrict__ W)
{
    int bid = blockIdx.x;

    if (bid < AGG_BLKS) {
        __shared__ int s_idx[32];
        __shared__ int s_n;
        int b = bid >> 1;
        int half = bid & 1;

        if (threadIdx.x < 32) {
            // int64 labels (values 0/1) have all odd 32-bit words zero
            const int* l32 = (const int*)label_raw;
            int nz = 0;
            for (int i = threadIdx.x; i < 64; i += 32)
                if (l32[2 * i + 1] != 0) nz = 1;
            unsigned any = __ballot_sync(0xffffffffu, nz);
            int is_i64 = (any == 0u);

            int pred;
            if (is_i64) {
                const long long* l = (const long long*)label_raw;
                pred = (l[(size_t)b * Aa + threadIdx.x] > 0);
            } else {
                const int* l = (const int*)label_raw;
                pred = (l[(size_t)b * Aa + threadIdx.x] > 0);
            }
            unsigned m = __ballot_sync(0xffffffffu, pred);
            if (pred) s_idx[__popc(m & ((1u << threadIdx.x) - 1u))] = threadIdx.x;
            if (threadIdx.x == 0) s_n = __popc(m);
        }
        __syncthreads();
        int nact = s_n;

        const float4* f4 = reinterpret_cast<const float4*>(feat) + (size_t)b * Aa * (Dd / 4);
        __nv_bfloat162* hi2 = reinterpret_cast<__nv_bfloat162*>(g_Ahi + (size_t)b * Dd);
        __nv_bfloat162* lo2 = reinterpret_cast<__nv_bfloat162*>(g_Alo + (size_t)b * Dd);

        int i = half * 256 + threadIdx.x;
        float4 s = make_float4(0.f, 0.f, 0.f, 0.f);
#pragma unroll 4
        for (int j = 0; j < nact; j++) {
            float4 v = ldcs4(&f4[(size_t)s_idx[j] * (Dd / 4) + i]);
            s.x += v.x; s.y += v.y; s.z += v.z; s.w += v.w;
        }
        float vals[4] = {s.x, s.y, s.z, s.w};
        __nv_bfloat16 h[4], l[4];
#pragma unroll
        for (int j = 0; j < 4; j++) {
            h[j] = __float2bfloat16(vals[j]);
            l[j] = __float2bfloat16(vals[j] - __bfloat162float(h[j]));
        }
        hi2[i * 2 + 0] = __nv_bfloat162(h[0], h[1]);
        hi2[i * 2 + 1] = __nv_bfloat162(h[2], h[3]);
        lo2[i * 2 + 0] = __nv_bfloat162(l[0], l[1]);
        lo2[i * 2 + 1] = __nv_bfloat162(l[2], l[3]);
    } else {
        const float4* W4 = (const float4*)W;
        __nv_bfloat162* hi2 = (__nv_bfloat162*)g_Whi;
        __nv_bfloat162* lo2 = (__nv_bfloat162*)g_Wlo;
        int base = (bid - AGG_BLKS) * 1024 + threadIdx.x;
#pragma unroll
        for (int u = 0; u < 4; u++) {
            int i = base + u * 256;
            float4 w = ldcs4(&W4[i]);
            float vals[4] = {w.x, w.y, w.z, w.w};
            __nv_bfloat16 h[4], l[4];
#pragma unroll
            for (int j = 0; j < 4; j++) {
                h[j] = __float2bfloat16(vals[j]);
                l[j] = __float2bfloat16(vals[j] - __bfloat162float(h[j]));
            }
            hi2[i * 2 + 0] = __nv_bfloat162(h[0], h[1]);
            hi2[i * 2 + 1] = __nv_bfloat162(h[2], h[3]);
            lo2[i * 2 + 0] = __nv_bfloat162(l[0], l[1]);
            lo2[i * 2 + 1] = __nv_bfloat162(l[2], l[3]);
        }
    }
}

// ---------------------------------------------------------------------------
// bf16 GEMM via mma.sync. CTA tile 128(m) x 128(n), 4-way K-split + 3 terms
// across blockIdx.z (grid 16 x 2 x 12 = 384 CTAs, K=512 per CTA).
// 8 warps = 4(m) x 2(n); warp tile 32 x 64 (warp-n owns one 64-col B half).
// 16 chunks of k32, 4-stage cp.async pipeline, one commit-group per iteration.
// A SMEM: [m128][k32] 64B rows. B SMEM: two [k32][n64] 4KB halves, 128B rows,
// consumed via ldmatrix.x4.trans (exact R8 formulas per half).
// ---------------------------------------------------------------------------
static constexpr int STAGE_BYTES = 16384;    // A 8KB + B 2x4KB
static constexpr int NSTAGE = 4;
static constexpr int NCHUNK = 16;            // 512 / 32
static constexpr int GEMM_SMEM = NSTAGE * STAGE_BYTES;   // 64 KB dynamic

__global__ __launch_bounds__(256) void gemm_kernel() {
    extern __shared__ __align__(128) char smbuf[];
    const uint32_t sbase = smem_u32(smbuf);

    const int tid = threadIdx.x;
    const int lane = tid & 31;
    const int wid = tid >> 5;
    const int wm = wid >> 1;          // warp m (0..3)
    const int wn = wid & 1;           // warp n half (0/1)

    const int n0 = blockIdx.x * 128;
    const int m0 = blockIdx.y * 128;
    const int zz = blockIdx.z;        // 0..11
    const int term = zz >> 2;         // 0: Ahi*Whi, 1: Ahi*Wlo, 2: Alo*Whi
    const int kz = zz & 3;
    const int kbase0 = kz * 512;

    const __nv_bfloat16* Ap = (term == 2) ? g_Alo : g_Ahi;
    const __nv_bfloat16* Bp = (term == 1) ? g_Wlo : g_Whi;
    const __nv_bfloat16* Ag = Ap + (size_t)m0 * Dd + kbase0;      // [m][k]
    const __nv_bfloat16* Bg = Bp + (size_t)kbase0 * Dd + n0;      // [k][n]

    const int g = lane >> 3;
    const int lr = lane & 7;

    // ldmatrix A offsets: rows 64B, swizzle c^((row>>1)&3). [mt][ks]
    uint32_t offA[2][2];
#pragma unroll
    for (int mt = 0; mt < 2; mt++) {
        int row = wm * 32 + mt * 16 + (g & 1) * 8 + lr;
#pragma unroll
        for (int ks = 0; ks < 2; ks++) {
            int c = 2 * ks + (g >> 1);
            offA[mt][ks] = row * 64 + ((c ^ ((row >> 1) & 3)) << 4);
        }
    }
    // ldmatrix B offsets (trans) within this warp's 4KB half: rows 128B,
    // swizzle c^(krow&7). [ks][q], q covers n16 each (4 per k16 for n64).
    const uint32_t bhalf = 8192 + wn * 4096;
    uint32_t offB[2][4];
#pragma unroll
    for (int ks = 0; ks < 2; ks++) {
        int krow = ks * 16 + (g & 1) * 8 + lr;
#pragma unroll
        for (int q = 0; q < 4; q++) {
            int c = 2 * q + (g >> 1);
            offB[ks][q] = bhalf + krow * 128 + ((c ^ (krow & 7)) << 4);
        }
    }

    // cp.async: A 8KB -> 2 chunks/thread; B 8KB -> 2 chunks/thread (one per half)
    const int arow = tid >> 2, ac = tid & 3;
    const uint32_t aoff = arow * 64 + ((ac ^ ((arow >> 1) & 3)) << 4);
    const int brow = tid >> 3, bc = tid & 7;
    const uint32_t boff = brow * 128 + ((bc ^ (brow & 7)) << 4);

    auto issue_load = [&](int chunk) {
        int kt = chunk * 32;
        uint32_t st = sbase + (chunk & (NSTAGE - 1)) * STAGE_BYTES;
        cp_async16(st + aoff, Ag + (size_t)arow * Dd + kt + ac * 8);
        cp_async16(st + aoff + 4096, Ag + (size_t)(arow + 64) * Dd + kt + ac * 8);
        cp_async16(st + 8192 + boff, Bg + (size_t)(kt + brow) * Dd + bc * 8);
        cp_async16(st + 12288 + boff, Bg + (size_t)(kt + brow) * Dd + 64 + bc * 8);
        cp_commit();
    };

    float acc[2][8][4];
#pragma unroll
    for (int mt = 0; mt < 2; mt++)
#pragma unroll
        for (int nf = 0; nf < 8; nf++)
#pragma unroll
            for (int k = 0; k < 4; k++) acc[mt][nf][k] = 0.f;

    issue_load(0); issue_load(1); issue_load(2);

    for (int i = 0; i < NCHUNK; i++) {
        // chunk i's group was committed 3 iterations ago; with exactly one
        // commit per iteration, wait_group 2 guarantees stage i has landed.
        asm volatile("cp.async.wait_group 2;" ::: "memory");
        __syncthreads();
        if (i + 3 < NCHUNK) issue_load(i + 3);
        else cp_commit();                      // empty group keeps accounting exact

        uint32_t st = sbase + (i & (NSTAGE - 1)) * STAGE_BYTES;

#pragma unroll
        for (int ks = 0; ks < 2; ks++) {
            uint32_t a[2][4], b[4][4];
            ldsm4(a[0][0], a[0][1], a[0][2], a[0][3], st + offA[0][ks]);
            ldsm4(a[1][0], a[1][1], a[1][2], a[1][3], st + offA[1][ks]);
#pragma unroll
            for (int q = 0; q < 4; q++)
                ldsm4t(b[q][0], b[q][1], b[q][2], b[q][3], st + offB[ks][q]);

#pragma unroll
            for (int mt = 0; mt < 2; mt++)
#pragma unroll
                for (int q = 0; q < 4; q++) {
                    mma16816(acc[mt][2 * q + 0], a[mt], b[q][0], b[q][1]);
                    mma16816(acc[mt][2 * q + 1], a[mt], b[q][2], b[q][3]);
                }
        }
    }
    asm volatile("cp.async.wait_group 0;" ::: "memory");

    // direct epilogue: warp owns rows [wm*32, wm*32+32), cols [wn*64, wn*64+64)
    float* gp = g_part[zz];
#pragma unroll
    for (int mt = 0; mt < 2; mt++)
#pragma unroll
        for (int nf = 0; nf < 8; nf++) {
            int grow = m0 + wm * 32 + mt * 16 + (lane >> 2);
            int gcol = n0 + wn * 64 + nf * 8 + (lane & 3) * 2;
            *(float2*)&gp[(size_t)grow * Dd + gcol] =
                make_float2(acc[mt][nf][0], acc[mt][nf][1]);
            *(float2*)&gp[(size_t)(grow + 8) * Dd + gcol] =
                make_float2(acc[mt][nf][2], acc[mt][nf][3]);
        }
}

// ---------------------------------------------------------------------------
// finish: out = tanh(sum of 12 partials + bias)   (fixed order -> deterministic)
// ---------------------------------------------------------------------------
__global__ __launch_bounds__(256) void finish_kernel(
    const float* __restrict__ bias, float* __restrict__ out)
{
    int idx = blockIdx.x * 256 + threadIdx.x;        // float4 index
    int n4 = idx & (Dd / 4 - 1);
    float4 s = make_float4(0.f, 0.f, 0.f, 0.f);
#pragma unroll
    for (int p = 0; p < 12; p++) {
        float4 v = ((const float4*)g_part[p])[idx];
        s.x += v.x; s.y += v.y; s.z += v.z; s.w += v.w;
    }
    float4 bv = ((const float4*)bias)[n4];
    float4 r;
    r.x = tanhf(s.x + bv.x);
    r.y = tanhf(s.y + bv.y);
    r.z = tanhf(s.z + bv.z);
    r.w = tanhf(s.w + bv.w);
    ((float4*)out)[idx] = r;
}

// ---------------------------------------------------------------------------
// launch: inputs x, attribute_feat, attribute_label, W, b  (x unused: adj[A][A]=0)
// ---------------------------------------------------------------------------
extern "C" void kernel_launch(void* const* d_in, const int* in_sizes, int n_in,
                              void* d_out, int out_size) {
    (void)in_sizes; (void)n_in; (void)out_size;
    const float* feat  = (const float*)d_in[1];
    const void*  label = d_in[2];
    const float* W     = (const float*)d_in[3];
    const float* bias  = (const float*)d_in[4];
    float* out = (float*)d_out;

    cudaFuncSetAttribute(gemm_kernel, cudaFuncAttributeMaxDynamicSharedMemorySize, GEMM_SMEM);

    prep_kernel<<<AGG_BLKS + CVT_BLKS, 256>>>(feat, label, W);
    gemm_kernel<<<dim3(Dd / 128, Bb / 128, 12), 256, GEMM_SMEM>>>();
    finish_kernel<<<(Bb * Dd / 4) / 256, 256>>>(bias, out);
}